// round 2
// baseline (speedup 1.0000x reference)
#include <cuda_runtime.h>
#include <math.h>

#define D 4096
#define HID 4096
#define STEPS 16
#define FUS (5 * D)
#define SPLITK 64
#define ESPLIT 16
#define RES_SCALE 0.1f

// ---------------- scratch (single __device__ array, no allocations) ----------------
#define OFF_FUSION   0                        // 20480
#define OFF_HBUF     (OFF_FUSION + FUS)       // 4096
#define OFF_COND     (OFF_HBUF + HID)         // 4096
#define OFF_STATE    (OFF_COND + D)           // 4096
#define OFF_CONDC    (OFF_STATE + D)          // 4096  condition-part of in_w1 (+in_b1)
#define OFF_EMBC     (OFF_CONDC + D)          // 16*4096
#define OFF_H1       (OFF_EMBC + STEPS * D)   // 4096
#define OFF_X        (OFF_H1 + D)             // 4096
#define OFF_GI       (OFF_X + D)              // 12288
#define OFF_GH       (OFF_GI + 3 * D)         // 12288
#define OFF_PART     (OFF_GH + 3 * D)         // SPLITK*4096
#define OFF_PARTE    (OFF_PART + SPLITK * D)  // ESPLIT*STEPS*4096
#define OFF_DOTS     (OFF_PARTE + ESPLIT * STEPS * D) // 17
#define SCRATCH_TOTAL (OFF_DOTS + 32)

__device__ float g_scratch[SCRATCH_TOTAL];

// ---------------- helpers ----------------
__device__ __forceinline__ float gelu_exact(float v) {
    return 0.5f * v * (1.0f + erff(v * 0.7071067811865476f));
}
__device__ __forceinline__ float sigmoidf(float v) {
    return 1.0f / (1.0f + expf(-v));
}

// ---------------- kernels ----------------

// fusion = [a, p, c, p-a, p*a]
__global__ void k_fusion(const float* __restrict__ a, const float* __restrict__ p,
                         const float* __restrict__ c) {
    int i = blockIdx.x * blockDim.x + threadIdx.x;
    float av = a[i], pv = p[i], cv = c[i];
    float* f = g_scratch + OFF_FUSION;
    f[i] = av; f[D + i] = pv; f[2 * D + i] = cv;
    f[3 * D + i] = pv - av; f[4 * D + i] = pv * av;
}

// Col-major GEMV partial: W is [K, 4096] row-major; out[j] = sum_k x[k]*W[k][j].
// grid.x = 4096/(256*4) = 4, grid.y = SPLITK. Each thread: 4 consecutive j via float4.
__global__ void k_gemv_col_part(const float* __restrict__ W, const float* __restrict__ x,
                                int K, float* __restrict__ part) {
    int j4 = (blockIdx.x * blockDim.x + threadIdx.x) * 4;
    int ks = (int)(((long long)K * blockIdx.y) / gridDim.y);
    int ke = (int)(((long long)K * (blockIdx.y + 1)) / gridDim.y);
    float4 acc = make_float4(0.f, 0.f, 0.f, 0.f);
    #pragma unroll 4
    for (int k = ks; k < ke; k++) {
        float xv = __ldg(&x[k]);
        float4 w = *(const float4*)(W + (size_t)k * D + j4);
        acc.x = fmaf(xv, w.x, acc.x);
        acc.y = fmaf(xv, w.y, acc.y);
        acc.z = fmaf(xv, w.z, acc.z);
        acc.w = fmaf(xv, w.w, acc.w);
    }
    *(float4*)(part + (size_t)blockIdx.y * D + j4) = acc;
}

// Finish: sum partials, add optional vectors/bias, optional GELU, optional scale+residual.
__global__ void k_gemv_col_fin(const float* __restrict__ part, int splitk,
                               const float* __restrict__ add0, const float* __restrict__ add1,
                               const float* __restrict__ bias, int act, float scale,
                               const float* __restrict__ residual, float* __restrict__ out) {
    int j = blockIdx.x * blockDim.x + threadIdx.x;
    float s = 0.f;
    for (int t = 0; t < splitk; t++) s += part[(size_t)t * D + j];
    if (add0) s += add0[j];
    if (add1) s += add1[j];
    if (bias) s += bias[j];
    if (act) s = gelu_exact(s);
    if (residual) out[j] = residual[j] + scale * s;
    else out[j] = scale * s;
}

// Step-embedding contribution: out[t][j] = sum_k emb[t][k]*We[k][j] (We = in_w1 rows [2D,3D))
__global__ void k_emb_part(const float* __restrict__ We, const float* __restrict__ emb,
                           float* __restrict__ part) {
    int j = blockIdx.x * blockDim.x + threadIdx.x;
    int ks = blockIdx.y * (D / ESPLIT);
    int ke = ks + (D / ESPLIT);
    float acc[STEPS];
    #pragma unroll
    for (int t = 0; t < STEPS; t++) acc[t] = 0.f;
    for (int k = ks; k < ke; k++) {
        float w = __ldg(&We[(size_t)k * D + j]);
        #pragma unroll
        for (int t = 0; t < STEPS; t++)
            acc[t] = fmaf(__ldg(&emb[t * D + k]), w, acc[t]);
    }
    #pragma unroll
    for (int t = 0; t < STEPS; t++)
        part[((size_t)blockIdx.y * STEPS + t) * D + j] = acc[t];
}

__global__ void k_emb_fin(const float* __restrict__ part, float* __restrict__ out) {
    int idx = blockIdx.x * blockDim.x + threadIdx.x; // t*D + j
    float s = 0.f;
    #pragma unroll
    for (int sp = 0; sp < ESPLIT; sp++) s += part[(size_t)sp * STEPS * D + idx];
    out[idx] = s;
}

// Row-major GEMV: out[r] = dot(W[r,:], x) + bias[r]. One warp per row.
__global__ void k_gemv_row(const float* __restrict__ W, const float* __restrict__ x,
                           const float* __restrict__ bias, float* __restrict__ out) {
    int warp = threadIdx.x >> 5, lane = threadIdx.x & 31;
    int row = blockIdx.x * (blockDim.x >> 5) + warp;
    const float4* Wr = (const float4*)(W + (size_t)row * D);
    const float4* xv = (const float4*)x;
    float acc = 0.f;
    #pragma unroll 4
    for (int i = lane; i < D / 4; i += 32) {
        float4 w = Wr[i];
        float4 xx = __ldg(&xv[i]);
        acc += w.x * xx.x + w.y * xx.y + w.z * xx.z + w.w * xx.w;
    }
    #pragma unroll
    for (int o = 16; o > 0; o >>= 1) acc += __shfl_down_sync(0xffffffffu, acc, o);
    if (lane == 0) out[row] = acc + bias[row];
}

// GRU combine + LayerNorm, single block of 1024 threads (D=4096 -> 4 elems/thread)
__global__ void k_gru_ln(const float* __restrict__ gi, const float* __restrict__ gh,
                         float* __restrict__ state, float* __restrict__ st_out,
                         const float* __restrict__ lng, const float* __restrict__ lnb) {
    __shared__ float red1[32], red2[32];
    int tid = threadIdx.x;
    float h[4];
    float s = 0.f, s2 = 0.f;
    #pragma unroll
    for (int u = 0; u < 4; u++) {
        int e = tid + u * 1024;
        float ir = gi[e], iz = gi[D + e], inn = gi[2 * D + e];
        float hr = gh[e], hz = gh[D + e], hn = gh[2 * D + e];
        float r = sigmoidf(ir + hr);
        float z = sigmoidf(iz + hz);
        float n = tanhf(inn + r * hn);
        float st = state[e];
        float hv = (1.f - z) * n + z * st;
        h[u] = hv; s += hv; s2 += hv * hv;
    }
    #pragma unroll
    for (int o = 16; o > 0; o >>= 1) {
        s  += __shfl_down_sync(0xffffffffu, s, o);
        s2 += __shfl_down_sync(0xffffffffu, s2, o);
    }
    if ((tid & 31) == 0) { red1[tid >> 5] = s; red2[tid >> 5] = s2; }
    __syncthreads();
    if (tid < 32) {
        s = red1[tid]; s2 = red2[tid];
        #pragma unroll
        for (int o = 16; o > 0; o >>= 1) {
            s  += __shfl_down_sync(0xffffffffu, s, o);
            s2 += __shfl_down_sync(0xffffffffu, s2, o);
        }
        if (tid == 0) { red1[0] = s; red2[0] = s2; }
    }
    __syncthreads();
    float mean = red1[0] * (1.f / (float)D);
    float var = red2[0] * (1.f / (float)D) - mean * mean;
    float rstd = rsqrtf(var + 1e-5f);
    #pragma unroll
    for (int u = 0; u < 4; u++) {
        int e = tid + u * 1024;
        float hv = h[u];
        st_out[e] = (hv - mean) * rstd * lng[e] + lnb[e];
        state[e] = hv;
    }
}

// 17 dot products: dots[t] = states[t].gate_w[0:D]  (t<16), dots[16] = condition.gate_w[D:2D]
__global__ void k_gate_dots(const float* __restrict__ states, const float* __restrict__ cond,
                            const float* __restrict__ gw, float* __restrict__ dots) {
    int warp = threadIdx.x >> 5, lane = threadIdx.x & 31;
    if (warp > 16) return;
    const float* vec = (warp < 16) ? (states + (size_t)warp * D) : cond;
    const float* w   = (warp < 16) ? gw : (gw + D);
    float acc = 0.f;
    for (int i = lane; i < D; i += 32) acc += vec[i] * w[i];
    #pragma unroll
    for (int o = 16; o > 0; o >>= 1) acc += __shfl_down_sync(0xffffffffu, acc, o);
    if (lane == 0) dots[warp] = acc;
}

__global__ void k_summary(const float* __restrict__ states, const float* __restrict__ dots,
                          const float* __restrict__ gate_b, float* __restrict__ out) {
    int j = blockIdx.x * blockDim.x + threadIdx.x;
    float cd = dots[16] + gate_b[0];
    float num = 0.f, den = 0.f;
    #pragma unroll
    for (int t = 0; t < STEPS; t++) {
        float g = sigmoidf(dots[t] + cd);
        num = fmaf(g, states[(size_t)t * D + j], num);
        den += g;
    }
    out[j] = num / fmaxf(den, 1e-6f);
}

// ---------------- host ----------------
static void run_gemv_col(const float* W, const float* x, int K, float* part,
                         const float* add0, const float* add1, const float* bias,
                         int act, float scale, const float* residual, float* out) {
    dim3 grid(D / (256 * 4), SPLITK);
    k_gemv_col_part<<<grid, 256>>>(W, x, K, part);
    k_gemv_col_fin<<<D / 256, 256>>>(part, SPLITK, add0, add1, bias, act, scale, residual, out);
}

extern "C" void kernel_launch(void* const* d_in, const int* in_sizes, int n_in,
                              void* d_out, int out_size) {
    const float* anchor   = (const float*)d_in[0];
    const float* proposal = (const float*)d_in[1];
    const float* context  = (const float*)d_in[2];
    const float* seed_w1  = (const float*)d_in[3];
    const float* seed_b1  = (const float*)d_in[4];
    const float* seed_w2  = (const float*)d_in[5];
    const float* seed_b2  = (const float*)d_in[6];
    const float* cond_w1  = (const float*)d_in[7];
    const float* cond_b1  = (const float*)d_in[8];
    const float* cond_w2  = (const float*)d_in[9];
    const float* cond_b2  = (const float*)d_in[10];
    const float* in_w1    = (const float*)d_in[11];
    const float* in_b1    = (const float*)d_in[12];
    const float* in_w2    = (const float*)d_in[13];
    const float* in_b2    = (const float*)d_in[14];
    const float* step_emb = (const float*)d_in[15];
    const float* w_ih     = (const float*)d_in[16];
    const float* b_ih     = (const float*)d_in[17];
    const float* w_hh     = (const float*)d_in[18];
    const float* b_hh     = (const float*)d_in[19];
    const float* ln_g     = (const float*)d_in[20];
    const float* ln_b     = (const float*)d_in[21];
    const float* gate_w   = (const float*)d_in[22];
    const float* gate_b   = (const float*)d_in[23];

    float* S = nullptr;
    cudaGetSymbolAddress((void**)&S, g_scratch);

    float* fusion    = S + OFF_FUSION;
    float* hbuf      = S + OFF_HBUF;
    float* condition = S + OFF_COND;
    float* state     = S + OFF_STATE;
    float* cond_c    = S + OFF_CONDC;
    float* emb_c     = S + OFF_EMBC;
    float* h1        = S + OFF_H1;
    float* xbuf      = S + OFF_X;
    float* gi        = S + OFF_GI;
    float* gh        = S + OFF_GH;
    float* part      = S + OFF_PART;
    float* part_e    = S + OFF_PARTE;
    float* dots      = S + OFF_DOTS;

    float* states  = (float*)d_out;               // [16, 4096]
    float* summary = (float*)d_out + STEPS * D;   // [4096]

    // fusion vector
    k_fusion<<<D / 256, 256>>>(anchor, proposal, context);

    // condition = MLP_cond(fusion)
    run_gemv_col(cond_w1, fusion, FUS, part, nullptr, nullptr, cond_b1, 1, 1.f, nullptr, hbuf);
    run_gemv_col(cond_w2, hbuf, D, part, nullptr, nullptr, cond_b2, 0, 1.f, nullptr, condition);

    // state0 = p + 0.1 * MLP_seed(fusion)
    run_gemv_col(seed_w1, fusion, FUS, part, nullptr, nullptr, seed_b1, 1, 1.f, nullptr, hbuf);
    run_gemv_col(seed_w2, hbuf, D, part, nullptr, nullptr, seed_b2, 0, RES_SCALE, proposal, state);

    // hoisted: condition contribution of in_w1 (rows [0,D)) + in_b1 folded here
    run_gemv_col(in_w1, condition, D, part, nullptr, nullptr, in_b1, 0, 1.f, nullptr, cond_c);

    // hoisted: step-embedding contributions of in_w1 (rows [2D,3D)) for all 16 steps
    k_emb_part<<<dim3(D / 256, ESPLIT), 256>>>(in_w1 + (size_t)2 * D * D, step_emb, part_e);
    k_emb_fin<<<(STEPS * D) / 256, 256>>>(part_e, emb_c);

    // 16 sequential GRU steps
    for (int t = 0; t < STEPS; t++) {
        // h1 = GELU(cond_c + emb_c[t] + state @ in_w1[D:2D])
        run_gemv_col(in_w1 + (size_t)D * D, state, D, part, cond_c, emb_c + (size_t)t * D,
                     nullptr, 1, 1.f, nullptr, h1);
        // x = h1 @ in_w2 + in_b2
        run_gemv_col(in_w2, h1, D, part, nullptr, nullptr, in_b2, 0, 1.f, nullptr, xbuf);
        // gi = W_ih @ x + b_ih ; gh = W_hh @ state + b_hh
        k_gemv_row<<<(3 * D) / 8, 256>>>(w_ih, xbuf, b_ih, gi);
        k_gemv_row<<<(3 * D) / 8, 256>>>(w_hh, state, b_hh, gh);
        // GRU combine + LN -> states[t], state updated
        k_gru_ln<<<1, 1024>>>(gi, gh, state, states + (size_t)t * D, ln_g, ln_b);
    }

    // gated summary
    k_gate_dots<<<1, 544>>>(states, condition, gate_w, dots);
    k_summary<<<D / 256, 256>>>(states, dots, gate_b, summary);
}